// round 10
// baseline (speedup 1.0000x reference)
#include <cuda_runtime.h>
#include <math.h>

#define D 128
#define WIN 128
#define BATCH 8
#define SEQ 8192
#define STR 132                        // smem row stride in floats (k-major rows)
#define GB_OFF (3 * 128 * STR)         // gelu(beta) table after 3 buffers
#define SMEM_BYTES ((3 * 128 * STR + 128 + 1024) * 4)
#define SCALE 0.08838834764831845f     // 1/sqrt(128)

typedef unsigned long long ull;

// Fused weights, row-major [d][j]:  g_M = (Wq Wk^T)*SCALE,  g_N = Wv Wo
__device__ float g_M[D * D];
__device__ float g_N[D * D];

// ---------------- f32x2 helpers ----------------
__device__ __forceinline__ ull pk(float x, float y) {
    ull r;
    asm("mov.b64 %0, {%1, %2};" : "=l"(r) : "f"(x), "f"(y));
    return r;
}
__device__ __forceinline__ void upk(ull v, float& x, float& y) {
    asm("mov.b64 {%0, %1}, %2;" : "=f"(x), "=f"(y) : "l"(v));
}
__device__ __forceinline__ void fma2(ull& d, ull a, ull b) {
    asm("fma.rn.f32x2 %0, %1, %2, %0;" : "+l"(d) : "l"(a), "l"(b));
}
__device__ __forceinline__ float gelu(float y) {
    return 0.5f * y * (1.f + erff(y * 0.70710678118654752f));
}

// ---------------------------------------------------------------------------
// Precompute fused weights. grid=256: blocks 0..127 -> M row d, 128..255 -> N.
// ---------------------------------------------------------------------------
__global__ void __launch_bounds__(128, 8)
precompute_kernel(const float* __restrict__ Wq, const float* __restrict__ Wk,
                  const float* __restrict__ Wv, const float* __restrict__ Wo) {
    __shared__ float w[D];
    int t = threadIdx.x;
    if (blockIdx.x < 128) {
        int d = blockIdx.x;
        w[t] = Wq[d * D + t];
        __syncthreads();
        const float4* row = (const float4*)(Wk + t * D);
        float a0 = 0.f, a1 = 0.f, a2 = 0.f, a3 = 0.f;
        #pragma unroll
        for (int f4 = 0; f4 < 32; f4 += 4) {
            float4 k0 = __ldg(&row[f4 + 0]);
            float4 k1 = __ldg(&row[f4 + 1]);
            float4 k2 = __ldg(&row[f4 + 2]);
            float4 k3 = __ldg(&row[f4 + 3]);
            a0 += w[f4*4+0]*k0.x + w[f4*4+1]*k0.y + w[f4*4+2]*k0.z + w[f4*4+3]*k0.w;
            a1 += w[f4*4+4]*k1.x + w[f4*4+5]*k1.y + w[f4*4+6]*k1.z + w[f4*4+7]*k1.w;
            a2 += w[f4*4+8]*k2.x + w[f4*4+9]*k2.y + w[f4*4+10]*k2.z + w[f4*4+11]*k2.w;
            a3 += w[f4*4+12]*k3.x + w[f4*4+13]*k3.y + w[f4*4+14]*k3.z + w[f4*4+15]*k3.w;
        }
        g_M[d * D + t] = (a0 + a1 + a2 + a3) * SCALE;
    } else {
        int d = blockIdx.x - 128;
        w[t] = Wv[d * D + t];
        __syncthreads();
        float a0 = 0.f, a1 = 0.f, a2 = 0.f, a3 = 0.f;
        #pragma unroll 8
        for (int f = 0; f < D; f += 4) {
            a0 += w[f + 0] * __ldg(&Wo[(f + 0) * D + t]);
            a1 += w[f + 1] * __ldg(&Wo[(f + 1) * D + t]);
            a2 += w[f + 2] * __ldg(&Wo[(f + 2) * D + t]);
            a3 += w[f + 3] * __ldg(&Wo[(f + 3) * D + t]);
        }
        g_N[d * D + t] = a0 + a1 + a2 + a3;
    }
}

// ---------------------------------------------------------------------------
// 8x4 register-tile GEMM, row-paired f32x2 accumulators.
//   Thread tile: rows i0..i0+7, cols cA..cA+3.
//   a: 2 LDS.128 (4 distinct 16B addrs, 8-way broadcast) -> 1 wavefront each
//   b: 1 LDS.128 (8 distinct 16B addrs, one 128B window) -> 1 wavefront
//   acc[rp*4+c] = (C[i0+2rp][cA+c], C[i0+2rp+1][cA+c])
// ---------------------------------------------------------------------------
__device__ __forceinline__ void gemm8x4(const float* __restrict__ A,
                                        const float* __restrict__ B,
                                        int i0, int cA, ull acc[16]) {
    #pragma unroll
    for (int q = 0; q < 16; q++) acc[q] = 0ull;

    const float* ar = A + i0;
    const float* br = B + cA;
    #pragma unroll 4
    for (int k = 0; k < D; k++) {
        float4 a0 = *(const float4*)(ar);
        float4 a1 = *(const float4*)(ar + 4);
        float4 b0 = *(const float4*)(br);
        ar += STR; br += STR;
        ull ap[4];
        ap[0] = pk(a0.x, a0.y);
        ap[1] = pk(a0.z, a0.w);
        ap[2] = pk(a1.x, a1.y);
        ap[3] = pk(a1.z, a1.w);
        float bv[4] = {b0.x, b0.y, b0.z, b0.w};
        #pragma unroll
        for (int c = 0; c < 4; c++) {
            ull bd = pk(bv[c], bv[c]);
            fma2(acc[0 * 4 + c], ap[0], bd);
            fma2(acc[1 * 4 + c], ap[1], bd);
            fma2(acc[2 * 4 + c], ap[2], bd);
            fma2(acc[3 * 4 + c], ap[3], bd);
        }
    }
}

// Unpack row-paired acc into v[row][col]
__device__ __forceinline__ void unpack8x4(const ull acc[16], float v[8][4]) {
    #pragma unroll
    for (int rp = 0; rp < 4; rp++)
        #pragma unroll
        for (int c = 0; c < 4; c++)
            upk(acc[rp * 4 + c], v[2 * rp][c], v[2 * rp + 1][c]);
}

// Store v into buf (row-major stride STR) at rows i0.., cols cA..
__device__ __forceinline__ void store8x4(float* buf, int i0, int cA,
                                         const float v[8][4]) {
    #pragma unroll
    for (int r = 0; r < 8; r++)
        *(float4*)&buf[(i0 + r) * STR + cA] =
            make_float4(v[r][0], v[r][1], v[r][2], v[r][3]);
}

// ---------------------------------------------------------------------------
// Main fused kernel: one CTA per (batch, 128-token block). 512 threads.
// Warp grid 4(rows) x 4(cols): warp (wr, wc) covers rows wr*32..+31,
// cols wc*32..+31. Lane: lr = l>>3 -> rows i0 = wr*32+lr*8 (8 rows);
// lc = l&7 -> cols cA = wc*32+lc*4 (4 cols).
// Row reductions: width-8 shfl + 4-way cross-warp combine via smem.
// ---------------------------------------------------------------------------
__global__ void __launch_bounds__(512, 1)
attn_kernel(const float* __restrict__ x, const float* __restrict__ gamma,
            const float* __restrict__ beta, float* __restrict__ out) {
    extern __shared__ float sm[];
    float* sX = sm;
    float* sW = sm + 128 * STR;
    float* sV = sm + 2 * 128 * STR;
    float* sGB = sm + GB_OFF;
    float* redM = sGB + 128;           // [4][128]
    float* redS = redM + 512;          // [4][128]

    const int tid = threadIdx.x;
    const int wid = tid >> 5;
    const int wr = wid & 3, wc = wid >> 2;
    const int l = tid & 31;
    const int lr = l >> 3, lc = l & 7;
    const int i0 = wr * 32 + lr * 8;
    const int cA = wc * 32 + lc * 4;
    const int blk = blockIdx.x;
    const int b = blk >> 6, n = blk & 63;

    // ---- stage X^T, M, N; gelu(beta) table ----
    {
        const float4* Xg4 = (const float4*)(x + (b * SEQ + n * WIN) * D);
        const float4* M4 = (const float4*)g_M;
        const float4* N4 = (const float4*)g_N;
        #pragma unroll 4
        for (int i = tid; i < 4096; i += 512) {
            int r = i >> 5;            // row (token for X, k for W)
            int c4 = (i & 31) * 4;     // feature base
            float4 v = Xg4[i];
            sX[(c4 + 0) * STR + r] = v.x;
            sX[(c4 + 1) * STR + r] = v.y;
            sX[(c4 + 2) * STR + r] = v.z;
            sX[(c4 + 3) * STR + r] = v.w;
            *(float4*)&sW[r * STR + c4] = M4[i];
            *(float4*)&sV[r * STR + c4] = N4[i];
        }
        if (tid < 128) sGB[tid] = gelu(beta[tid]);
    }
    __syncthreads();

    // ---- constant half block: out[b][S + n*WIN ..] = gelu(beta) ----
    {
        float4* dst = (float4*)(out + ((size_t)b * 2 * SEQ + SEQ + n * WIN) * D);
        #pragma unroll
        for (int q = 0; q < 8; q++) {
            int idx = q * 512 + tid;       // coalesced float4 index
            int c = (idx & 31) * 4;
            dst[idx] = make_float4(sGB[c], sGB[c + 1], sGB[c + 2], sGB[c + 3]);
        }
    }

    ull acc[16];
    float v[8][4];

    // ---- G1: T^T[j][i] = sum_d M[d][j] * X^T[d][i]  (scale folded in M) ----
    gemm8x4(sW, sX, i0, cA, acc);      // rows = j, cols = i
    unpack8x4(acc, v);
    __syncthreads();                   // all G1 reads of sW done
    store8x4(sW, i0, cA, v);
    __syncthreads();

    // ---- G2: S[i][u] = sum_f T^T[f][i] * X^T[f][u] ----
    gemm8x4(sW, sX, i0, cA, acc);      // rows = i, cols = u
    unpack8x4(acc, v);

    // ---- softmax over u: width-8 shfl + 4-way warp combine via smem ----
    {
        float gm[8];
        #pragma unroll
        for (int r = 0; r < 8; r++) {
            float m = fmaxf(fmaxf(v[r][0], v[r][1]), fmaxf(v[r][2], v[r][3]));
            #pragma unroll
            for (int off = 4; off; off >>= 1)
                m = fmaxf(m, __shfl_xor_sync(0xffffffffu, m, off, 8));
            gm[r] = m;
        }
        if (lc == 0) {
            #pragma unroll
            for (int r = 0; r < 8; r++) redM[wc * 128 + i0 + r] = gm[r];
        }
        __syncthreads();               // also: all threads past G2 reads of sW
        float gs[8];
        #pragma unroll
        for (int r = 0; r < 8; r++) {
            int ro = i0 + r;
            float m = fmaxf(fmaxf(redM[ro], redM[128 + ro]),
                            fmaxf(redM[256 + ro], redM[384 + ro]));
            float s = 0.f;
            #pragma unroll
            for (int c = 0; c < 4; c++) {
                v[r][c] = __expf(v[r][c] - m);
                s += v[r][c];
            }
            #pragma unroll
            for (int off = 4; off; off >>= 1)
                s += __shfl_xor_sync(0xffffffffu, s, off, 8);
            gs[r] = s;
        }
        if (lc == 0) {
            #pragma unroll
            for (int r = 0; r < 8; r++) redS[wc * 128 + i0 + r] = gs[r];
        }
        __syncthreads();
        #pragma unroll
        for (int r = 0; r < 8; r++) {
            int ro = i0 + r;
            float inv = 1.0f / (redS[ro] + redS[128 + ro] +
                                redS[256 + ro] + redS[384 + ro]);
            #pragma unroll
            for (int c = 0; c < 4; c++) v[r][c] *= inv;
        }
    }

    // ---- store P^T[u][i] into sW (all sW reads done at softmax barrier) ----
    #pragma unroll
    for (int c = 0; c < 4; c++) {
        *(float4*)&sW[(cA + c) * STR + i0] =
            make_float4(v[0][c], v[1][c], v[2][c], v[3][c]);
        *(float4*)&sW[(cA + c) * STR + i0 + 4] =
            make_float4(v[4][c], v[5][c], v[6][c], v[7][c]);
    }

    // ---- G3: U[u][d] = sum_f X^T[f][u] * N[f][d]  (doesn't touch sW) ----
    gemm8x4(sX, sV, i0, cA, acc);      // rows = u, cols = d
    unpack8x4(acc, v);
    __syncthreads();                   // G3 reads of sV done; P^T visible
    store8x4(sV, i0, cA, v);
    __syncthreads();

    // ---- G4: H[i][d] = sum_u P^T[u][i] * U[u][d] ----
    gemm8x4(sW, sV, i0, cA, acc);      // rows = i, cols = d
    unpack8x4(acc, v);

    // ---- LayerNorm + exact GELU + store ----
    {
        float gs[8];
        #pragma unroll
        for (int r = 0; r < 8; r++) {
            float s = v[r][0] + v[r][1] + v[r][2] + v[r][3];
            #pragma unroll
            for (int off = 4; off; off >>= 1)
                s += __shfl_xor_sync(0xffffffffu, s, off, 8);
            gs[r] = s;
        }
        if (lc == 0) {
            #pragma unroll
            for (int r = 0; r < 8; r++) redM[wc * 128 + i0 + r] = gs[r];
        }
        __syncthreads();
        float gv[8], mu[8];
        #pragma unroll
        for (int r = 0; r < 8; r++) {
            int ro = i0 + r;
            mu[r] = (redM[ro] + redM[128 + ro] + redM[256 + ro] +
                     redM[384 + ro]) * (1.0f / 128.0f);
            float var = 0.f;
            #pragma unroll
            for (int c = 0; c < 4; c++) {
                float dlt = v[r][c] - mu[r];
                var += dlt * dlt;
            }
            #pragma unroll
            for (int off = 4; off; off >>= 1)
                var += __shfl_xor_sync(0xffffffffu, var, off, 8);
            gv[r] = var;
        }
        if (lc == 0) {
            #pragma unroll
            for (int r = 0; r < 8; r++) redS[wc * 128 + i0 + r] = gv[r];
        }
        __syncthreads();

        float4 ga = *(const float4*)(gamma + cA);
        float4 ba = *(const float4*)(beta + cA);
        float gc[4] = {ga.x, ga.y, ga.z, ga.w};
        float bc[4] = {ba.x, ba.y, ba.z, ba.w};

        float* outp = out + ((size_t)b * 2 * SEQ + n * WIN) * D;
        #pragma unroll
        for (int r = 0; r < 8; r++) {
            int ro = i0 + r;
            float var = redS[ro] + redS[128 + ro] + redS[256 + ro] +
                        redS[384 + ro];
            float rstd = rsqrtf(var * (1.0f / 128.0f) + 1e-5f);
            float o[4];
            #pragma unroll
            for (int c = 0; c < 4; c++)
                o[c] = gelu((v[r][c] - mu[r]) * rstd * gc[c] + bc[c]);
            *(float4*)&outp[ro * D + cA] = make_float4(o[0], o[1], o[2], o[3]);
        }
    }
}

// ---------------------------------------------------------------------------
extern "C" void kernel_launch(void* const* d_in, const int* in_sizes, int n_in,
                              void* d_out, int out_size) {
    const float* x     = (const float*)d_in[0];
    const float* Wq    = (const float*)d_in[1];
    const float* Wk    = (const float*)d_in[2];
    const float* Wv    = (const float*)d_in[3];
    const float* Wo    = (const float*)d_in[4];
    const float* gamma = (const float*)d_in[5];
    const float* beta  = (const float*)d_in[6];
    float* out = (float*)d_out;

    cudaFuncSetAttribute(attn_kernel,
                         cudaFuncAttributeMaxDynamicSharedMemorySize,
                         SMEM_BYTES);

    precompute_kernel<<<256, 128>>>(Wq, Wk, Wv, Wo);
    attn_kernel<<<BATCH * (SEQ / WIN), 512, SMEM_BYTES>>>(x, gamma, beta, out);
}